// round 1
// baseline (speedup 1.0000x reference)
#include <cuda_runtime.h>

#define NN 8192
#define TPB 256
#define JPT (NN / TPB)   // 32 j's per thread

// Packed per-point data: {theta, tau, cos(theta), sin(theta)}
__device__ float4 g_packed[NN];

__global__ void prep_kernel(const float* __restrict__ theta,
                            const float* __restrict__ tau) {
    int i = blockIdx.x * blockDim.x + threadIdx.x;
    if (i < NN) {
        float t = theta[i];
        float s, c;
        sincosf(t, &s, &c);
        g_packed[i] = make_float4(t, tau[i], c, s);
    }
}

__device__ __forceinline__ float warp_sum(float v) {
#pragma unroll
    for (int o = 16; o > 0; o >>= 1) v += __shfl_down_sync(0xffffffffu, v, o);
    return v;
}

__global__ void __launch_bounds__(TPB, 1)
row_kernel(float* __restrict__ out_theta,
           float* __restrict__ out_tau,
           float* __restrict__ out_attn) {
    __shared__ __align__(16) float sm_e[NN];     // unnormalized scores for this row
    __shared__ float red[6][TPB / 32];
    __shared__ float sm_inv;

    const int i = blockIdx.x;
    const int t = threadIdx.x;

    const float4 pi = g_packed[i];
    const float th_i = pi.x, ta_i = pi.y, c_i = pi.z, s_i = pi.w;

    const float TWO_PI = 6.28318530717958647692f;
    const float CEXP   = -3.60673760222240851f;   // -2.5 * log2(e)

    float sum = 0.f, ax = 0.f, ay = 0.f, at = 0.f, fx = 0.f, fy = 0.f;

#pragma unroll 8
    for (int k = 0; k < JPT; k++) {
        const int j = t + k * TPB;
        const float4 pj = g_packed[j];

        // angular + tau distance
        float ad   = fabsf(th_i - pj.x);
        float dth  = fminf(ad, TWO_PI - ad);
        float dta  = fabsf(ta_i - pj.y);
        float dist = fmaf(0.3f, dta, dth);

        // score = exp(-2.5 * dist) = exp2(dist * CEXP)  (single MUFU.EX2)
        float e;
        asm("ex2.approx.f32 %0, %1;" : "=f"(e) : "f"(dist * CEXP));

        sum += e;
        ax = fmaf(e, pj.z, ax);
        ay = fmaf(e, pj.w, ay);
        at = fmaf(e, pj.y, at);
        sm_e[j] = e;

        // repulsion: 0.15 / ((dth+0.1)^2 * (sqrt(dx^2+dy^2) + 1e-8)) * (dx, dy)
        float d  = dth + 0.1f;
        float t2 = d * d;
        float dx = c_i - pj.z;
        float dy = s_i - pj.w;
        float n2 = fmaf(dx, dx, dy * dy);
        float sn;
        asm("sqrt.approx.f32 %0, %1;" : "=f"(sn) : "f"(n2));      // MUFU.SQRT
        float denom = t2 * (sn + 1e-8f);
        float r;
        asm("rcp.approx.f32 %0, %1;" : "=f"(r) : "f"(denom));     // MUFU.RCP
        float w = 0.15f * r;
        fx = fmaf(w, dx, fx);   // at j==i: dx=dy=0 -> exact 0 contribution
        fy = fmaf(w, dy, fy);
    }
    __syncthreads();

    // block reduction of the 6 accumulators
    sum = warp_sum(sum); ax = warp_sum(ax); ay = warp_sum(ay);
    at  = warp_sum(at);  fx = warp_sum(fx); fy = warp_sum(fy);
    const int lane = t & 31, wid = t >> 5;
    if (lane == 0) {
        red[0][wid] = sum; red[1][wid] = ax; red[2][wid] = ay;
        red[3][wid] = at;  red[4][wid] = fx; red[5][wid] = fy;
    }
    __syncthreads();

    if (t == 0) {
        float S = 0.f, AX = 0.f, AY = 0.f, AT = 0.f, FX = 0.f, FY = 0.f;
#pragma unroll
        for (int w = 0; w < TPB / 32; w++) {
            S += red[0][w]; AX += red[1][w]; AY += red[2][w];
            AT += red[3][w]; FX += red[4][w]; FY += red[5][w];
        }
        // remove self contribution: e(i,i)=exp2(0)=1 exactly
        S  -= 1.0f;
        AX -= c_i;
        AY -= s_i;
        AT -= ta_i;

        const float inv = 1.0f / S;
        const float Rx = AX * inv + FX;
        const float Ry = AY * inv + FY;
        out_theta[i] = atan2f(Ry, Rx);
        out_tau[i]   = AT * inv;
        sm_inv  = inv;
        sm_e[i] = 0.0f;      // diagonal of attn is zero
    }
    __syncthreads();

    // normalize + write attn row (coalesced float4 stores)
    const float inv = sm_inv;
    float4* attn4 = reinterpret_cast<float4*>(out_attn + (size_t)i * NN);
    const float4* e4 = reinterpret_cast<const float4*>(sm_e);
#pragma unroll
    for (int k = 0; k < JPT / 4; k++) {
        const int idx = t + k * TPB;
        float4 v = e4[idx];
        v.x *= inv; v.y *= inv; v.z *= inv; v.w *= inv;
        attn4[idx] = v;
    }
}

extern "C" void kernel_launch(void* const* d_in, const int* in_sizes, int n_in,
                              void* d_out, int out_size) {
    const float* theta = (const float*)d_in[0];
    const float* tau   = (const float*)d_in[1];
    float* out = (float*)d_out;

    float* out_theta = out;
    float* out_tau   = out + NN;
    float* out_attn  = out + 2 * NN;

    prep_kernel<<<(NN + 255) / 256, 256>>>(theta, tau);
    row_kernel<<<NN, TPB>>>(out_theta, out_tau, out_attn);
}

// round 2
// speedup vs baseline: 1.0074x; 1.0074x over previous
#include <cuda_runtime.h>
#include <math.h>

#define NN 8192
#define TPB 256
#define NP (NN / 2)
#define PPT (NP / TPB)          // 16 packed (2-point) iterations per thread

typedef unsigned long long u64;

// Pair-interleaved tables:
// g_A[p] = {theta_2p, theta_2p+1, tau_2p, tau_2p+1}
// g_B[p] = {-cos_2p, -cos_2p+1, -sin_2p, -sin_2p+1}
__device__ __align__(16) float4 g_A[NP];
__device__ __align__(16) float4 g_B[NP];

__global__ void prep_kernel(const float* __restrict__ th,
                            const float* __restrict__ ta) {
    int k = blockIdx.x * blockDim.x + threadIdx.x;
    if (k < NP) {
        float t0 = th[2 * k], t1 = th[2 * k + 1];
        float s0, c0, s1, c1;
        sincosf(t0, &s0, &c0);
        sincosf(t1, &s1, &c1);
        g_A[k] = make_float4(t0, t1, ta[2 * k], ta[2 * k + 1]);
        g_B[k] = make_float4(-c0, -c1, -s0, -s1);
    }
}

// ---- packed f32x2 helpers ----
__device__ __forceinline__ u64 pk2(float lo, float hi) {
    u64 r; asm("mov.b64 %0, {%1,%2};" : "=l"(r) : "f"(lo), "f"(hi)); return r;
}
__device__ __forceinline__ void unpk(float& lo, float& hi, u64 v) {
    asm("mov.b64 {%0,%1}, %2;" : "=f"(lo), "=f"(hi) : "l"(v));
}
__device__ __forceinline__ u64 addx2(u64 a, u64 b) {
    u64 r; asm("add.rn.f32x2 %0, %1, %2;" : "=l"(r) : "l"(a), "l"(b)); return r;
}
__device__ __forceinline__ u64 mulx2(u64 a, u64 b) {
    u64 r; asm("mul.rn.f32x2 %0, %1, %2;" : "=l"(r) : "l"(a), "l"(b)); return r;
}
__device__ __forceinline__ u64 fmx2(u64 a, u64 b, u64 c) {
    u64 r; asm("fma.rn.f32x2 %0, %1, %2, %3;" : "=l"(r) : "l"(a), "l"(b), "l"(c)); return r;
}
__device__ __forceinline__ float ex2a(float x) {
    float r; asm("ex2.approx.f32 %0, %1;" : "=f"(r) : "f"(x)); return r;
}
__device__ __forceinline__ float sqrta(float x) {
    float r; asm("sqrt.approx.f32 %0, %1;" : "=f"(r) : "f"(x)); return r;
}
__device__ __forceinline__ float rcpa(float x) {
    float r; asm("rcp.approx.f32 %0, %1;" : "=f"(r) : "f"(x)); return r;
}

__device__ __forceinline__ float warp_sum(float v) {
#pragma unroll
    for (int o = 16; o > 0; o >>= 1) v += __shfl_down_sync(0xffffffffu, v, o);
    return v;
}

__global__ void __launch_bounds__(TPB, 3)
row_kernel(float* __restrict__ out_theta,
           float* __restrict__ out_tau,
           float* __restrict__ out_attn) {
    __shared__ __align__(16) float sm_e[NN];
    __shared__ float red[6][TPB / 32];
    __shared__ float sm_inv;

    const int i = blockIdx.x;
    const int t = threadIdx.x;

    // row scalars (uniform across block)
    const float4 Ai = g_A[i >> 1];
    const float4 Bi = g_B[i >> 1];
    const bool od = (i & 1);
    const float th_i = od ? Ai.y : Ai.x;
    const float ta_i = od ? Ai.w : Ai.z;
    const float c_i = -(od ? Bi.y : Bi.x);
    const float s_i = -(od ? Bi.w : Bi.z);

    const float PI_F   = 3.14159265358979323846f;
    const float CEXP   = -3.60673760222240851f;      // -2.5 * log2(e)
    const float C3     = 0.3f * CEXP;                // tau weight folded in

    const u64 ABSM = 0x7FFFFFFF7FFFFFFFULL;
    const u64 NEGM = 0x8000000080000000ULL;

    const u64 nthI  = pk2(-th_i, -th_i);
    const u64 ntaI  = pk2(-ta_i, -ta_i);
    const u64 cI2   = pk2(c_i, c_i);
    const u64 sI2   = pk2(s_i, s_i);
    const u64 pi2   = pk2(PI_F, PI_F);
    const u64 npi2  = pk2(-PI_F, -PI_F);
    const u64 cexp2 = pk2(CEXP, CEXP);
    const u64 c32   = pk2(C3, C3);
    const u64 p012  = pk2(0.1f, 0.1f);

    const ulonglong2* __restrict__ A2 = reinterpret_cast<const ulonglong2*>(g_A);
    const ulonglong2* __restrict__ B2 = reinterpret_cast<const ulonglong2*>(g_B);
    u64* __restrict__ sme8 = reinterpret_cast<u64*>(sm_e);

    u64 sum2 = 0, at2 = 0, axn2 = 0, ayn2 = 0;      // packed accumulators (0.0f pairs)
    float fxa = 0.f, fxb = 0.f, fya = 0.f, fyb = 0.f;

#pragma unroll 8
    for (int k = 0; k < PPT; k++) {
        const int p = t + k * TPB;                  // packed index: points 2p, 2p+1
        const ulonglong2 a = A2[p];
        const ulonglong2 b = B2[p];
        const u64 thp = a.x, tap = a.y, ncp = b.x, nsp = b.y;

        // angular distance: dth = pi - ||dth_raw| - pi|
        u64 ad  = addx2(thp, nthI);
        u64 aa  = ad & ABSM;
        u64 cc  = addx2(aa, npi2);
        u64 ncc = cc | NEGM;                        // -|cc|
        u64 dth = addx2(pi2, ncc);

        // exp argument: CEXP*dth + (0.3*CEXP)*|dtau|
        u64 dta = addx2(tap, ntaI);
        u64 adt = dta & ABSM;
        u64 tA  = mulx2(adt, c32);
        u64 arg = fmx2(dth, cexp2, tA);

        float g0, g1; unpk(g0, g1, arg);
        float e0 = ex2a(g0);
        float e1 = ex2a(g1);
        u64 epk = pk2(e0, e1);

        sum2 = addx2(sum2, epk);
        at2  = fmx2(epk, tap, at2);
        axn2 = fmx2(epk, ncp, axn2);                // -sum(e*c_j)
        ayn2 = fmx2(epk, nsp, ayn2);                // -sum(e*s_j)
        sme8[p] = epk;                              // STS.64

        // repulsion
        u64 d   = addx2(dth, p012);
        u64 t2  = mulx2(d, d);
        u64 dx  = addx2(cI2, ncp);                  // c_i - c_j (exact 0 at j==i)
        u64 dy  = addx2(sI2, nsp);
        u64 m   = mulx2(dx, dx);
        u64 n2  = fmx2(dy, dy, m);

        float n2a, n2b; unpk(n2a, n2b, n2);
        float t2a, t2b; unpk(t2a, t2b, t2);
        float dxa, dxb; unpk(dxa, dxb, dx);
        float dya, dyb; unpk(dya, dyb, dy);

        float sna = sqrta(n2a);
        float snb = sqrta(n2b);
        float ra = rcpa(t2a * (sna + 1e-8f));
        float rb = rcpa(t2b * (snb + 1e-8f));
        fxa = fmaf(ra, dxa, fxa);
        fya = fmaf(ra, dya, fya);
        fxb = fmaf(rb, dxb, fxb);
        fyb = fmaf(rb, dyb, fyb);
    }
    __syncthreads();

    // combine packed halves -> 6 scalars, then block-reduce
    float s0, s1, x0, x1, y0, y1, u0, u1;
    unpk(s0, s1, sum2);
    unpk(x0, x1, axn2);
    unpk(y0, y1, ayn2);
    unpk(u0, u1, at2);
    float sum = s0 + s1;
    float axn = x0 + x1;
    float ayn = y0 + y1;
    float at  = u0 + u1;
    float fx  = fxa + fxb;
    float fy  = fya + fyb;

    sum = warp_sum(sum); axn = warp_sum(axn); ayn = warp_sum(ayn);
    at  = warp_sum(at);  fx  = warp_sum(fx);  fy  = warp_sum(fy);
    const int lane = t & 31, wid = t >> 5;
    if (lane == 0) {
        red[0][wid] = sum; red[1][wid] = axn; red[2][wid] = ayn;
        red[3][wid] = at;  red[4][wid] = fx;  red[5][wid] = fy;
    }
    __syncthreads();

    if (t == 0) {
        float S = 0.f, AXN = 0.f, AYN = 0.f, AT = 0.f, FX = 0.f, FY = 0.f;
#pragma unroll
        for (int w = 0; w < TPB / 32; w++) {
            S += red[0][w]; AXN += red[1][w]; AYN += red[2][w];
            AT += red[3][w]; FX += red[4][w]; FY += red[5][w];
        }
        // self contribution: e(i,i)=1 exactly
        S -= 1.0f;
        float AX = -AXN - c_i;
        float AY = -AYN - s_i;
        AT -= ta_i;

        const float inv = 1.0f / S;
        const float Rx = AX * inv + 0.15f * FX;
        const float Ry = AY * inv + 0.15f * FY;
        out_theta[i] = atan2f(Ry, Rx);
        out_tau[i]   = AT * inv;
        sm_inv = inv;
        sm_e[i] = 0.0f;                 // attn diagonal
    }
    __syncthreads();

    // normalize + write attn row
    const float inv = sm_inv;
    float4* attn4 = reinterpret_cast<float4*>(out_attn + (size_t)i * NN);
    const float4* e4 = reinterpret_cast<const float4*>(sm_e);
#pragma unroll
    for (int k = 0; k < NN / 4 / TPB; k++) {
        const int idx = t + k * TPB;
        float4 v = e4[idx];
        v.x *= inv; v.y *= inv; v.z *= inv; v.w *= inv;
        attn4[idx] = v;
    }
}

extern "C" void kernel_launch(void* const* d_in, const int* in_sizes, int n_in,
                              void* d_out, int out_size) {
    const float* theta = (const float*)d_in[0];
    const float* tau   = (const float*)d_in[1];
    float* out = (float*)d_out;

    float* out_theta = out;
    float* out_tau   = out + NN;
    float* out_attn  = out + 2 * NN;

    prep_kernel<<<(NP + 255) / 256, 256>>>(theta, tau);
    row_kernel<<<NN, TPB>>>(out_theta, out_tau, out_attn);
}